// round 4
// baseline (speedup 1.0000x reference)
#include <cuda_runtime.h>
#include <cuda_bf16.h>
#include <cstdint>

#define D 128
#define TMG 128            // rows per GEMM tile
#define WS_S 132           // padded smem stride (mult of 4 for float4 reads)
#define MAX_NODES 100000
#define MAX_EDGES 3200000

// Scratch (device globals: no runtime allocation allowed)
__device__ float  g_y[(size_t)MAX_NODES * D];        // y = x @ W^T + b   (51.2 MB)
__device__ int    g_deg[MAX_NODES];
__device__ int    g_offs[MAX_NODES + 1];
__device__ int    g_cursor[MAX_NODES];
__device__ float2 g_epack[MAX_EDGES];                // {val, bitcast(col)} row-sorted

__device__ __forceinline__ void cp_async16(uint32_t saddr, const void* gaddr) {
    asm volatile("cp.async.cg.shared.global [%0], [%1], 16;\n"
                 :: "r"(saddr), "l"(gaddr));
}
__device__ __forceinline__ void cp_async_commit() {
    asm volatile("cp.async.commit_group;\n" ::: "memory");
}
__device__ __forceinline__ void cp_async_wait_all() {
    asm volatile("cp.async.wait_group 0;\n" ::: "memory");
}

// ---------------------------------------------------------------------------
// Persistent GEMM: each CTA (one per SM) processes a contiguous range of
// 128-row tiles across BOTH GEMMs (tile t < tiles_per_gemm -> W/b -> y;
// else W_self/b_self -> out). W transpose amortized; x tile double-buffered.
// 256 threads, 8x8 micro-tile per thread.
// ---------------------------------------------------------------------------
__global__ void __launch_bounds__(256, 1)
gemm_persist(const float* __restrict__ x,
             const float* __restrict__ W0, const float* __restrict__ b0,
             const float* __restrict__ W1, const float* __restrict__ b1,
             float* __restrict__ y, float* __restrict__ out,
             int n_nodes, int tiles_per_gemm, int total_tiles)
{
    extern __shared__ float sm[];
    float* ws = sm;                         // [128][WS_S], ws[k*WS_S+j] = W[j][k]
    float* xs0 = sm + D * WS_S;             // [128][WS_S] buffer 0
    float* xs1 = xs0 + D * WS_S;            // buffer 1

    const int tid  = threadIdx.x;
    const int bid  = blockIdx.x;
    const int nblk = gridDim.x;

    int start = (int)(((long long)bid * total_tiles) / nblk);
    int end   = (int)(((long long)(bid + 1) * total_tiles) / nblk);
    if (start >= end) return;

    uint32_t xs_sm[2];
    xs_sm[0] = (uint32_t)__cvta_generic_to_shared(xs0);
    xs_sm[1] = (uint32_t)__cvta_generic_to_shared(xs1);
    float* xs_ptr[2] = { xs0, xs1 };

    const int tx = tid & 15;    // 16 col-groups (8 cols each)
    const int ty = tid >> 4;    // 16 row-groups (8 rows each)

    // Prefetch x tile for first tile into buffer 0
    {
        int m0 = ((start >= tiles_per_gemm) ? start - tiles_per_gemm : start) * TMG;
        #pragma unroll
        for (int q = 0; q < 16; ++q) {
            int idx = tid + q * 256;
            int m  = idx >> 5;
            int kq = idx & 31;
            int node = m0 + m; if (node >= n_nodes) node = n_nodes - 1;
            cp_async16(xs_sm[0] + (uint32_t)(m * WS_S + kq * 4) * 4,
                       x + (size_t)node * D + kq * 4);
        }
        cp_async_commit();
    }

    int cur_g = -1;
    int buf = 0;

    for (int t = start; t < end; ++t) {
        int g  = (t >= tiles_per_gemm) ? 1 : 0;
        int m0 = (t - g * tiles_per_gemm) * TMG;

        cp_async_wait_all();           // xs[buf] ready

        if (g != cur_g) {
            __syncthreads();           // prior compute done before ws overwrite
            const float* W = g ? W1 : W0;
            // scalar loads: lanes k-consecutive -> coalesced LDG + 4-way STS
            #pragma unroll 8
            for (int i = tid; i < D * D; i += 256) {
                int j = i >> 7, k = i & 127;
                ws[k * WS_S + j] = W[i];
            }
            cur_g = g;
        }
        __syncthreads();               // xs + ws visible

        // Prefetch next tile's x into the other buffer
        if (t + 1 < end) {
            int tn  = t + 1;
            int gn  = (tn >= tiles_per_gemm) ? 1 : 0;
            int m0n = (tn - gn * tiles_per_gemm) * TMG;
            #pragma unroll
            for (int q = 0; q < 16; ++q) {
                int idx = tid + q * 256;
                int m  = idx >> 5;
                int kq = idx & 31;
                int node = m0n + m; if (node >= n_nodes) node = n_nodes - 1;
                cp_async16(xs_sm[buf ^ 1] + (uint32_t)(m * WS_S + kq * 4) * 4,
                           x + (size_t)node * D + kq * 4);
            }
            cp_async_commit();
        }

        // ---- compute 128x128 tile, 8x8 per thread ----
        const float* xs = xs_ptr[buf];
        float acc[8][8];
        #pragma unroll
        for (int i = 0; i < 8; ++i)
            #pragma unroll
            for (int j = 0; j < 8; ++j) acc[i][j] = 0.f;

        const float4* ws4 = reinterpret_cast<const float4*>(ws);

        #pragma unroll 2
        for (int k = 0; k < D; ++k) {
            float4 wa = ws4[k * (WS_S / 4) + tx * 2];
            float4 wb = ws4[k * (WS_S / 4) + tx * 2 + 1];
            float xv[8];
            #pragma unroll
            for (int i = 0; i < 8; ++i)
                xv[i] = xs[(ty * 8 + i) * WS_S + k];
            #pragma unroll
            for (int i = 0; i < 8; ++i) {
                acc[i][0] += xv[i] * wa.x;
                acc[i][1] += xv[i] * wa.y;
                acc[i][2] += xv[i] * wa.z;
                acc[i][3] += xv[i] * wa.w;
                acc[i][4] += xv[i] * wb.x;
                acc[i][5] += xv[i] * wb.y;
                acc[i][6] += xv[i] * wb.z;
                acc[i][7] += xv[i] * wb.w;
            }
        }

        const float* bias = cur_g ? b1 : b0;
        float*       dst  = cur_g ? out : y;
        float4 ba = reinterpret_cast<const float4*>(bias)[tx * 2];
        float4 bb = reinterpret_cast<const float4*>(bias)[tx * 2 + 1];

        #pragma unroll
        for (int i = 0; i < 8; ++i) {
            int node = m0 + ty * 8 + i;
            if (node >= n_nodes) break;
            float4 oa = make_float4(acc[i][0] + ba.x, acc[i][1] + ba.y,
                                    acc[i][2] + ba.z, acc[i][3] + ba.w);
            float4 ob = make_float4(acc[i][4] + bb.x, acc[i][5] + bb.y,
                                    acc[i][6] + bb.z, acc[i][7] + bb.w);
            reinterpret_cast<float4*>(dst + (size_t)node * D)[tx * 2]     = oa;
            reinterpret_cast<float4*>(dst + (size_t)node * D)[tx * 2 + 1] = ob;
        }

        buf ^= 1;
    }
}

// ---------------------------------------------------------------------------
// CSR build
// ---------------------------------------------------------------------------
__global__ void __launch_bounds__(256)
hist_kernel(const int* __restrict__ erow, int n_edges)
{
    int i = blockIdx.x * blockDim.x + threadIdx.x;
    if (i < n_edges)
        atomicAdd(&g_deg[erow[i]], 1);
}

__global__ void __launch_bounds__(1024)
scan_kernel(int n)
{
    __shared__ int warp_sums[32];
    __shared__ int s_carry;
    int tid = threadIdx.x, lane = tid & 31, wid = tid >> 5;
    if (tid == 0) s_carry = 0;
    __syncthreads();

    for (int base = 0; base < n; base += 1024) {
        int i = base + tid;
        int v = (i < n) ? g_deg[i] : 0;
        int incl = v;
        #pragma unroll
        for (int d = 1; d < 32; d <<= 1) {
            int t = __shfl_up_sync(0xffffffffu, incl, d);
            if (lane >= d) incl += t;
        }
        if (lane == 31) warp_sums[wid] = incl;
        __syncthreads();
        if (wid == 0) {
            int s = warp_sums[lane];
            #pragma unroll
            for (int d = 1; d < 32; d <<= 1) {
                int t = __shfl_up_sync(0xffffffffu, s, d);
                if (lane >= d) s += t;
            }
            warp_sums[lane] = s;
        }
        __syncthreads();
        int warp_off = (wid == 0) ? 0 : warp_sums[wid - 1];
        int excl = s_carry + warp_off + incl - v;
        if (i < n) { g_offs[i] = excl; g_cursor[i] = excl; }
        __syncthreads();
        if (tid == 0) s_carry += warp_sums[31];
        __syncthreads();
    }
    if (threadIdx.x == 0) g_offs[n] = s_carry;
}

__global__ void __launch_bounds__(256)
scatter_kernel(const int* __restrict__ erow, const int* __restrict__ ecol,
               const float* __restrict__ eval_, int n_edges)
{
    int i = blockIdx.x * blockDim.x + threadIdx.x;
    if (i >= n_edges) return;
    int r = erow[i];
    int p = atomicAdd(&g_cursor[r], 1);
    g_epack[p] = make_float2(eval_[i], __int_as_float(ecol[i]));
}

// ---------------------------------------------------------------------------
// Gather: one warp per row; fused (+x2, relu)
// ---------------------------------------------------------------------------
__global__ void __launch_bounds__(256)
gather_kernel(const float* __restrict__ y, float* __restrict__ out, int n_nodes)
{
    int row  = blockIdx.x * (blockDim.x >> 5) + (threadIdx.x >> 5);
    int lane = threadIdx.x & 31;
    if (row >= n_nodes) return;

    int s = g_offs[row];
    int e = g_offs[row + 1];

    float4 acc = make_float4(0.f, 0.f, 0.f, 0.f);

    for (int base = s; base < e; base += 32) {
        int idx = base + lane;
        float2 p = make_float2(0.f, 0.f);
        if (idx < e) p = g_epack[idx];
        int cnt = min(32, e - base);

        int j = 0;
        for (; j + 4 <= cnt; j += 4) {
            float v0 = __shfl_sync(0xffffffffu, p.x, j);
            int   c0 = __float_as_int(__shfl_sync(0xffffffffu, p.y, j));
            float v1 = __shfl_sync(0xffffffffu, p.x, j + 1);
            int   c1 = __float_as_int(__shfl_sync(0xffffffffu, p.y, j + 1));
            float v2 = __shfl_sync(0xffffffffu, p.x, j + 2);
            int   c2 = __float_as_int(__shfl_sync(0xffffffffu, p.y, j + 2));
            float v3 = __shfl_sync(0xffffffffu, p.x, j + 3);
            int   c3 = __float_as_int(__shfl_sync(0xffffffffu, p.y, j + 3));

            float4 m0 = reinterpret_cast<const float4*>(y + (size_t)c0 * D)[lane];
            float4 m1 = reinterpret_cast<const float4*>(y + (size_t)c1 * D)[lane];
            float4 m2 = reinterpret_cast<const float4*>(y + (size_t)c2 * D)[lane];
            float4 m3 = reinterpret_cast<const float4*>(y + (size_t)c3 * D)[lane];

            acc.x += v0 * m0.x; acc.y += v0 * m0.y; acc.z += v0 * m0.z; acc.w += v0 * m0.w;
            acc.x += v1 * m1.x; acc.y += v1 * m1.y; acc.z += v1 * m1.z; acc.w += v1 * m1.w;
            acc.x += v2 * m2.x; acc.y += v2 * m2.y; acc.z += v2 * m2.z; acc.w += v2 * m2.w;
            acc.x += v3 * m3.x; acc.y += v3 * m3.y; acc.z += v3 * m3.z; acc.w += v3 * m3.w;
        }
        for (; j < cnt; ++j) {
            float vj = __shfl_sync(0xffffffffu, p.x, j);
            int   cj = __float_as_int(__shfl_sync(0xffffffffu, p.y, j));
            float4 m = reinterpret_cast<const float4*>(y + (size_t)cj * D)[lane];
            acc.x += vj * m.x; acc.y += vj * m.y; acc.z += vj * m.z; acc.w += vj * m.w;
        }
    }

    float4* orow = reinterpret_cast<float4*>(out + (size_t)row * D);
    float4 x2 = orow[lane];
    acc.x = fmaxf(acc.x + x2.x, 0.f);
    acc.y = fmaxf(acc.y + x2.y, 0.f);
    acc.z = fmaxf(acc.z + x2.z, 0.f);
    acc.w = fmaxf(acc.w + x2.w, 0.f);
    orow[lane] = acc;
}

extern "C" void kernel_launch(void* const* d_in, const int* in_sizes, int n_in,
                              void* d_out, int out_size)
{
    const float* x     = (const float*)d_in[0];
    const int*   erow  = (const int*)  d_in[1];
    const int*   ecol  = (const int*)  d_in[2];
    const float* eval_ = (const float*)d_in[3];
    const float* W     = (const float*)d_in[4];
    const float* b     = (const float*)d_in[5];
    const float* Wself = (const float*)d_in[6];
    const float* bself = (const float*)d_in[7];
    float* out = (float*)d_out;

    int n_nodes = in_sizes[0] / D;
    int n_edges = in_sizes[1];

    float* y;     cudaGetSymbolAddress((void**)&y, g_y);
    int*   degp;  cudaGetSymbolAddress((void**)&degp, g_deg);

    static cudaStream_t sB = nullptr;
    static cudaEvent_t  evFork = nullptr, evJoinB = nullptr;
    static int n_sms = 148;
    size_t smem = (size_t)(3 * D * WS_S) * sizeof(float);   // 202752 B
    if (!sB) {
        cudaStreamCreateWithFlags(&sB, cudaStreamNonBlocking);
        cudaEventCreateWithFlags(&evFork,  cudaEventDisableTiming);
        cudaEventCreateWithFlags(&evJoinB, cudaEventDisableTiming);
        cudaDeviceGetAttribute(&n_sms, cudaDevAttrMultiProcessorCount, 0);
        cudaFuncSetAttribute(gemm_persist,
                             cudaFuncAttributeMaxDynamicSharedMemorySize, (int)smem);
    }

    // Fork: CSR build on side stream, GEMMs on main stream.
    cudaEventRecord(evFork, 0);
    cudaStreamWaitEvent(sB, evFork, 0);

    cudaMemsetAsync(degp, 0, (size_t)n_nodes * sizeof(int), sB);
    hist_kernel<<<(n_edges + 255) / 256, 256, 0, sB>>>(erow, n_edges);
    scan_kernel<<<1, 1024, 0, sB>>>(n_nodes);
    scatter_kernel<<<(n_edges + 255) / 256, 256, 0, sB>>>(erow, ecol, eval_, n_edges);
    cudaEventRecord(evJoinB, sB);

    // Persistent GEMM over both weight matrices
    int tiles_per_gemm = (n_nodes + TMG - 1) / TMG;
    int total_tiles = 2 * tiles_per_gemm;
    gemm_persist<<<n_sms, 256, smem>>>(x, W, b, Wself, bself, y, out,
                                       n_nodes, tiles_per_gemm, total_tiles);

    cudaStreamWaitEvent(0, evJoinB, 0);
    int warps_per_block = 256 / 32;
    int gblocks = (n_nodes + warps_per_block - 1) / warps_per_block;
    gather_kernel<<<gblocks, 256>>>(y, out, n_nodes);
}

// round 5
// speedup vs baseline: 1.1355x; 1.1355x over previous
#include <cuda_runtime.h>
#include <cuda_bf16.h>
#include <cstdint>

#define D 128
#define TM 64              // nodes per GEMM block tile
#define WS_S 132           // padded smem stride for W (kills STS bank conflicts)
#define XS_S 132           // padded smem stride for x
#define MAX_NODES 100000
#define MAX_EDGES 3200000

// Scratch (device globals: no runtime allocation allowed)
__device__ float  g_y[(size_t)MAX_NODES * D];        // y = x @ W^T + b   (51.2 MB)
__device__ int    g_deg[MAX_NODES];
__device__ int    g_offs[MAX_NODES + 1];
__device__ int    g_cursor[MAX_NODES];
__device__ float2 g_epack[MAX_EDGES];                // {val, bitcast(col)} row-sorted

__device__ __forceinline__ void cp_async16(uint32_t saddr, const void* gaddr) {
    asm volatile("cp.async.cg.shared.global [%0], [%1], 16;\n"
                 :: "r"(saddr), "l"(gaddr));
}
__device__ __forceinline__ void cp_async_commit() {
    asm volatile("cp.async.commit_group;\n" ::: "memory");
}
__device__ __forceinline__ void cp_async_wait_all() {
    asm volatile("cp.async.wait_group 0;\n" ::: "memory");
}

// ---------------------------------------------------------------------------
// GEMM: out[n, j] = sum_k x[n,k] * W[j,k] + bias[j]
// blockIdx.y == 0 -> (W, b) -> g_y ; blockIdx.y == 1 -> (W_self, b_self) -> out
// 256 threads, 2 CTAs/SM (16 warps/SM). 4x8 micro-tile per thread.
// W transposed into smem with stride 132 -> 4-way STS conflicts (was 32-way).
// x tile loaded via cp.async, hidden under the W transpose.
// ---------------------------------------------------------------------------
__global__ void __launch_bounds__(256, 2)
gemm_kernel(const float* __restrict__ x,
            const float* __restrict__ W0, const float* __restrict__ b0,
            const float* __restrict__ W1, const float* __restrict__ b1,
            float* __restrict__ out0, float* __restrict__ out1,
            int n_nodes)
{
    extern __shared__ float sm[];
    float* ws = sm;                 // [128][WS_S], ws[k*WS_S+j] = W[j][k]
    float* xs = sm + D * WS_S;      // [TM][XS_S]

    const float* W    = blockIdx.y ? W1 : W0;
    const float* bias = blockIdx.y ? b1 : b0;
    float* out        = blockIdx.y ? out1 : out0;

    const int tid = threadIdx.x;
    const int m0  = blockIdx.x * TM;

    // Issue async x-tile load first (hides under W transpose below)
    {
        uint32_t xs_sm = (uint32_t)__cvta_generic_to_shared(xs);
        #pragma unroll
        for (int q = 0; q < 8; ++q) {          // TM*32 = 2048 quads, 8/thread
            int idx = tid + q * 256;
            int m  = idx >> 5;
            int kq = idx & 31;
            int node = m0 + m; if (node >= n_nodes) node = n_nodes - 1;
            cp_async16(xs_sm + (uint32_t)(m * XS_S + kq * 4) * 4,
                       x + (size_t)node * D + kq * 4);
        }
        cp_async_commit();
    }

    // W transpose into smem: coalesced LDG, 4-way-conflict STS (stride 132)
    #pragma unroll 8
    for (int i = tid; i < D * D; i += 256) {
        int j = i >> 7, k = i & 127;
        ws[k * WS_S + j] = W[i];
    }

    cp_async_wait_all();
    __syncthreads();

    const int tx = tid & 15;    // 16 col-groups (8 cols each: tx*8 .. tx*8+7)
    const int ty = tid >> 4;    // 16 row-groups (4 rows each)

    float acc[4][8];
    #pragma unroll
    for (int i = 0; i < 4; ++i)
        #pragma unroll
        for (int j = 0; j < 8; ++j) acc[i][j] = 0.f;

    const float4* ws4 = reinterpret_cast<const float4*>(ws);

    #pragma unroll 4
    for (int k = 0; k < D; ++k) {
        float4 wa = ws4[k * (WS_S / 4) + tx * 2];
        float4 wb = ws4[k * (WS_S / 4) + tx * 2 + 1];
        float xv[4];
        #pragma unroll
        for (int i = 0; i < 4; ++i)
            xv[i] = xs[(ty * 4 + i) * XS_S + k];
        #pragma unroll
        for (int i = 0; i < 4; ++i) {
            acc[i][0] += xv[i] * wa.x;
            acc[i][1] += xv[i] * wa.y;
            acc[i][2] += xv[i] * wa.z;
            acc[i][3] += xv[i] * wa.w;
            acc[i][4] += xv[i] * wb.x;
            acc[i][5] += xv[i] * wb.y;
            acc[i][6] += xv[i] * wb.z;
            acc[i][7] += xv[i] * wb.w;
        }
    }

    float4 ba = reinterpret_cast<const float4*>(bias)[tx * 2];
    float4 bb = reinterpret_cast<const float4*>(bias)[tx * 2 + 1];

    #pragma unroll
    for (int i = 0; i < 4; ++i) {
        int node = m0 + ty * 4 + i;
        if (node >= n_nodes) break;
        float4 oa = make_float4(acc[i][0] + ba.x, acc[i][1] + ba.y,
                                acc[i][2] + ba.z, acc[i][3] + ba.w);
        float4 ob = make_float4(acc[i][4] + bb.x, acc[i][5] + bb.y,
                                acc[i][6] + bb.z, acc[i][7] + bb.w);
        reinterpret_cast<float4*>(out + (size_t)node * D)[tx * 2]     = oa;
        reinterpret_cast<float4*>(out + (size_t)node * D)[tx * 2 + 1] = ob;
    }
}

// ---------------------------------------------------------------------------
// CSR build
// ---------------------------------------------------------------------------
__global__ void __launch_bounds__(256)
hist_kernel(const int* __restrict__ erow, int n_edges)
{
    int i = blockIdx.x * blockDim.x + threadIdx.x;
    if (i < n_edges)
        atomicAdd(&g_deg[erow[i]], 1);
}

__global__ void __launch_bounds__(1024)
scan_kernel(int n)
{
    __shared__ int warp_sums[32];
    __shared__ int s_carry;
    int tid = threadIdx.x, lane = tid & 31, wid = tid >> 5;
    if (tid == 0) s_carry = 0;
    __syncthreads();

    for (int base = 0; base < n; base += 1024) {
        int i = base + tid;
        int v = (i < n) ? g_deg[i] : 0;
        int incl = v;
        #pragma unroll
        for (int d = 1; d < 32; d <<= 1) {
            int t = __shfl_up_sync(0xffffffffu, incl, d);
            if (lane >= d) incl += t;
        }
        if (lane == 31) warp_sums[wid] = incl;
        __syncthreads();
        if (wid == 0) {
            int s = warp_sums[lane];
            #pragma unroll
            for (int d = 1; d < 32; d <<= 1) {
                int t = __shfl_up_sync(0xffffffffu, s, d);
                if (lane >= d) s += t;
            }
            warp_sums[lane] = s;
        }
        __syncthreads();
        int warp_off = (wid == 0) ? 0 : warp_sums[wid - 1];
        int excl = s_carry + warp_off + incl - v;
        if (i < n) { g_offs[i] = excl; g_cursor[i] = excl; }
        __syncthreads();
        if (tid == 0) s_carry += warp_sums[31];
        __syncthreads();
    }
    if (threadIdx.x == 0) g_offs[n] = s_carry;
}

__global__ void __launch_bounds__(256)
scatter_kernel(const int* __restrict__ erow, const int* __restrict__ ecol,
               const float* __restrict__ eval_, int n_edges)
{
    int i = blockIdx.x * blockDim.x + threadIdx.x;
    if (i >= n_edges) return;
    int r = erow[i];
    int p = atomicAdd(&g_cursor[r], 1);
    g_epack[p] = make_float2(eval_[i], __int_as_float(ecol[i]));
}

// ---------------------------------------------------------------------------
// Gather: one warp per row; fused (+x2, relu)
// ---------------------------------------------------------------------------
__global__ void __launch_bounds__(256)
gather_kernel(const float* __restrict__ y, float* __restrict__ out, int n_nodes)
{
    int row  = blockIdx.x * (blockDim.x >> 5) + (threadIdx.x >> 5);
    int lane = threadIdx.x & 31;
    if (row >= n_nodes) return;

    int s = g_offs[row];
    int e = g_offs[row + 1];

    float4 acc = make_float4(0.f, 0.f, 0.f, 0.f);

    for (int base = s; base < e; base += 32) {
        int idx = base + lane;
        float2 p = make_float2(0.f, 0.f);
        if (idx < e) p = g_epack[idx];
        int cnt = min(32, e - base);

        int j = 0;
        for (; j + 4 <= cnt; j += 4) {
            float v0 = __shfl_sync(0xffffffffu, p.x, j);
            int   c0 = __float_as_int(__shfl_sync(0xffffffffu, p.y, j));
            float v1 = __shfl_sync(0xffffffffu, p.x, j + 1);
            int   c1 = __float_as_int(__shfl_sync(0xffffffffu, p.y, j + 1));
            float v2 = __shfl_sync(0xffffffffu, p.x, j + 2);
            int   c2 = __float_as_int(__shfl_sync(0xffffffffu, p.y, j + 2));
            float v3 = __shfl_sync(0xffffffffu, p.x, j + 3);
            int   c3 = __float_as_int(__shfl_sync(0xffffffffu, p.y, j + 3));

            float4 m0 = reinterpret_cast<const float4*>(y + (size_t)c0 * D)[lane];
            float4 m1 = reinterpret_cast<const float4*>(y + (size_t)c1 * D)[lane];
            float4 m2 = reinterpret_cast<const float4*>(y + (size_t)c2 * D)[lane];
            float4 m3 = reinterpret_cast<const float4*>(y + (size_t)c3 * D)[lane];

            acc.x += v0 * m0.x; acc.y += v0 * m0.y; acc.z += v0 * m0.z; acc.w += v0 * m0.w;
            acc.x += v1 * m1.x; acc.y += v1 * m1.y; acc.z += v1 * m1.z; acc.w += v1 * m1.w;
            acc.x += v2 * m2.x; acc.y += v2 * m2.y; acc.z += v2 * m2.z; acc.w += v2 * m2.w;
            acc.x += v3 * m3.x; acc.y += v3 * m3.y; acc.z += v3 * m3.z; acc.w += v3 * m3.w;
        }
        for (; j < cnt; ++j) {
            float vj = __shfl_sync(0xffffffffu, p.x, j);
            int   cj = __float_as_int(__shfl_sync(0xffffffffu, p.y, j));
            float4 m = reinterpret_cast<const float4*>(y + (size_t)cj * D)[lane];
            acc.x += vj * m.x; acc.y += vj * m.y; acc.z += vj * m.z; acc.w += vj * m.w;
        }
    }

    float4* orow = reinterpret_cast<float4*>(out + (size_t)row * D);
    float4 x2 = orow[lane];
    acc.x = fmaxf(acc.x + x2.x, 0.f);
    acc.y = fmaxf(acc.y + x2.y, 0.f);
    acc.z = fmaxf(acc.z + x2.z, 0.f);
    acc.w = fmaxf(acc.w + x2.w, 0.f);
    orow[lane] = acc;
}

extern "C" void kernel_launch(void* const* d_in, const int* in_sizes, int n_in,
                              void* d_out, int out_size)
{
    const float* x     = (const float*)d_in[0];
    const int*   erow  = (const int*)  d_in[1];
    const int*   ecol  = (const int*)  d_in[2];
    const float* eval_ = (const float*)d_in[3];
    const float* W     = (const float*)d_in[4];
    const float* b     = (const float*)d_in[5];
    const float* Wself = (const float*)d_in[6];
    const float* bself = (const float*)d_in[7];
    float* out = (float*)d_out;

    int n_nodes = in_sizes[0] / D;
    int n_edges = in_sizes[1];

    float* y;     cudaGetSymbolAddress((void**)&y, g_y);
    int*   degp;  cudaGetSymbolAddress((void**)&degp, g_deg);

    static cudaStream_t sB = nullptr;
    static cudaEvent_t  evFork = nullptr, evJoinB = nullptr;
    size_t smem = (size_t)(D * WS_S + TM * XS_S) * sizeof(float);   // 101376 B
    if (!sB) {
        cudaStreamCreateWithFlags(&sB, cudaStreamNonBlocking);
        cudaEventCreateWithFlags(&evFork,  cudaEventDisableTiming);
        cudaEventCreateWithFlags(&evJoinB, cudaEventDisableTiming);
        cudaFuncSetAttribute(gemm_kernel,
                             cudaFuncAttributeMaxDynamicSharedMemorySize, (int)smem);
    }

    // Fork: CSR build on side stream, GEMMs on main stream.
    cudaEventRecord(evFork, 0);
    cudaStreamWaitEvent(sB, evFork, 0);

    cudaMemsetAsync(degp, 0, (size_t)n_nodes * sizeof(int), sB);
    hist_kernel<<<(n_edges + 255) / 256, 256, 0, sB>>>(erow, n_edges);
    scan_kernel<<<1, 1024, 0, sB>>>(n_nodes);
    scatter_kernel<<<(n_edges + 255) / 256, 256, 0, sB>>>(erow, ecol, eval_, n_edges);
    cudaEventRecord(evJoinB, sB);

    // GEMMs: y (scratch) and x2 (into out)
    dim3 grid((n_nodes + TM - 1) / TM, 2);
    gemm_kernel<<<grid, 256, smem>>>(x, W, b, Wself, bself, y, out, n_nodes);

    // Join, then fused gather (+x2, relu)
    cudaStreamWaitEvent(0, evJoinB, 0);
    int warps_per_block = 256 / 32;
    int gblocks = (n_nodes + warps_per_block - 1) / warps_per_block;
    gather_kernel<<<gblocks, 256>>>(y, out, n_nodes);
}

// round 7
// speedup vs baseline: 1.4115x; 1.2431x over previous
#include <cuda_runtime.h>
#include <cuda_bf16.h>
#include <cstdint>

#define D 128
#define TMG 128
#define XST 68              // smem row stride in 32-bit words (136 bf16) - conflict-free
#define MAX_NODES 100000
#define MAX_EDGES 3200000

// Scratch (device globals: no runtime allocation allowed)
__device__ float  g_y[(size_t)MAX_NODES * D];        // y = x @ W^T + b   (51.2 MB)
__device__ int    g_deg[MAX_NODES];
__device__ int    g_offs[MAX_NODES + 1];
__device__ int    g_cursor[MAX_NODES];
__device__ float2 g_epack[MAX_EDGES];                // {val, bitcast(col)} row-sorted

// smem word offsets (in uint32 units): 4 operand planes of [128][XST]
#define PLANE (128 * XST)                 // 8704 words = 34816 B
#define SM_WORDS (4 * PLANE)              // 139264 B total

__device__ __forceinline__ uint32_t pk_bf16x2(float a, float b) {
    return (uint32_t)__bfloat16_as_ushort(__float2bfloat16(a)) |
           ((uint32_t)__bfloat16_as_ushort(__float2bfloat16(b)) << 16);
}

__device__ __forceinline__ void mma16816(float* c, const uint32_t* a,
                                         uint32_t b0, uint32_t b1) {
    asm volatile(
        "mma.sync.aligned.m16n8k16.row.col.f32.bf16.bf16.f32 "
        "{%0,%1,%2,%3}, {%4,%5,%6,%7}, {%8,%9}, {%0,%1,%2,%3};"
        : "+f"(c[0]), "+f"(c[1]), "+f"(c[2]), "+f"(c[3])
        : "r"(a[0]), "r"(a[1]), "r"(a[2]), "r"(a[3]), "r"(b0), "r"(b1));
}

// ---------------------------------------------------------------------------
// bf16-split tensor-core GEMM: out[n,j] = sum_k x[n,k] * W[j,k] + bias[j]
// blockIdx.y==0 -> (W,b) -> g_y ; blockIdx.y==1 -> (W_self,b_self) -> out.
// 3 mma terms: xh*Wh + xh*Wl + xl*Wh  (lo*lo dropped; rel err ~3e-5).
// 8 warps: warp_m = wid&3 (32 rows), warp_n = wid>>2 (64 cols).
// ---------------------------------------------------------------------------
__global__ void __launch_bounds__(256, 1)
mma_gemm(const float* __restrict__ x,
         const float* __restrict__ W0, const float* __restrict__ b0,
         const float* __restrict__ W1, const float* __restrict__ b1,
         float* __restrict__ out0, float* __restrict__ out1,
         int n_nodes)
{
    extern __shared__ uint32_t sm[];
    uint32_t* XH = sm;
    uint32_t* XL = sm + PLANE;
    uint32_t* WH = sm + 2 * PLANE;
    uint32_t* WL = sm + 3 * PLANE;

    const float* W    = blockIdx.y ? W1 : W0;
    const float* bias = blockIdx.y ? b1 : b0;
    float* dst        = blockIdx.y ? out1 : out0;

    const int tid = threadIdx.x;
    const int m0  = blockIdx.x * TMG;

    // ---- convert x tile and W to bf16 hi/lo planes ----
    // 4096 float4 quads for W, 4096 for x; 16 each per thread.
    for (int i = tid; i < 4096; i += 256) {
        int r = i >> 5;           // row 0..127
        int q = i & 31;           // float4 index (cols 4q..4q+3)
        int wo = r * XST + q * 2; // word offset of the 4 bf16

        float4 wv = reinterpret_cast<const float4*>(W)[i];
        float hx = __bfloat162float(__float2bfloat16(wv.x));
        float hy = __bfloat162float(__float2bfloat16(wv.y));
        float hz = __bfloat162float(__float2bfloat16(wv.z));
        float hw = __bfloat162float(__float2bfloat16(wv.w));
        WH[wo]     = pk_bf16x2(wv.x, wv.y);
        WH[wo + 1] = pk_bf16x2(wv.z, wv.w);
        WL[wo]     = pk_bf16x2(wv.x - hx, wv.y - hy);
        WL[wo + 1] = pk_bf16x2(wv.z - hz, wv.w - hw);

        int node = m0 + r; if (node >= n_nodes) node = n_nodes - 1;
        float4 xv = reinterpret_cast<const float4*>(x + (size_t)node * D)[q];
        hx = __bfloat162float(__float2bfloat16(xv.x));
        hy = __bfloat162float(__float2bfloat16(xv.y));
        hz = __bfloat162float(__float2bfloat16(xv.z));
        hw = __bfloat162float(__float2bfloat16(xv.w));
        XH[wo]     = pk_bf16x2(xv.x, xv.y);
        XH[wo + 1] = pk_bf16x2(xv.z, xv.w);
        XL[wo]     = pk_bf16x2(xv.x - hx, xv.y - hy);
        XL[wo + 1] = pk_bf16x2(xv.z - hz, xv.w - hw);
    }
    __syncthreads();

    const int wid  = tid >> 5;
    const int lane = tid & 31;
    const int quad = lane >> 2;   // 0..7
    const int tq   = lane & 3;    // 0..3
    const int rowbase = (wid & 3) * 32;
    const int colbase = (wid >> 2) * 64;

    float acc[2][8][4];
    #pragma unroll
    for (int i = 0; i < 2; ++i)
        #pragma unroll
        for (int j = 0; j < 8; ++j)
            #pragma unroll
            for (int c = 0; c < 4; ++c) acc[i][j][c] = 0.f;

    const uint32_t* XB[3] = { XH, XH, XL };
    const uint32_t* WB[3] = { WH, WL, WH };

    for (int term = 0; term < 3; ++term) {
        const uint32_t* Xp = XB[term] + (rowbase + quad) * XST + tq;
        const uint32_t* Wp = WB[term] + (colbase + quad) * XST + tq;
        #pragma unroll
        for (int kst = 0; kst < 8; ++kst) {
            int ko = kst * 8;
            uint32_t a[2][4];
            #pragma unroll
            for (int i = 0; i < 2; ++i) {
                const uint32_t* p = Xp + i * 16 * XST + ko;
                a[i][0] = p[0];
                a[i][1] = p[8 * XST];
                a[i][2] = p[4];
                a[i][3] = p[8 * XST + 4];
            }
            #pragma unroll
            for (int j = 0; j < 8; ++j) {
                const uint32_t* p = Wp + j * 8 * XST + ko;
                uint32_t bb0 = p[0], bb1 = p[4];
                mma16816(acc[0][j], a[0], bb0, bb1);
                mma16816(acc[1][j], a[1], bb0, bb1);
            }
        }
    }

    // ---- epilogue: +bias, store fp32 ----
    float2 bias2[8];
    #pragma unroll
    for (int j = 0; j < 8; ++j)
        bias2[j] = *reinterpret_cast<const float2*>(bias + colbase + j * 8 + tq * 2);

    #pragma unroll
    for (int i = 0; i < 2; ++i) {
        int r0 = m0 + rowbase + i * 16 + quad;
        int r1 = r0 + 8;
        #pragma unroll
        for (int j = 0; j < 8; ++j) {
            int col = colbase + j * 8 + tq * 2;
            if (r0 < n_nodes) {
                float2 v = make_float2(acc[i][j][0] + bias2[j].x,
                                       acc[i][j][1] + bias2[j].y);
                *reinterpret_cast<float2*>(dst + (size_t)r0 * D + col) = v;
            }
            if (r1 < n_nodes) {
                float2 v = make_float2(acc[i][j][2] + bias2[j].x,
                                       acc[i][j][3] + bias2[j].y);
                *reinterpret_cast<float2*>(dst + (size_t)r1 * D + col) = v;
            }
        }
    }
}

// ---------------------------------------------------------------------------
// CSR build
// ---------------------------------------------------------------------------
__global__ void __launch_bounds__(256)
hist_kernel(const int* __restrict__ erow, int n_edges)
{
    int i = blockIdx.x * blockDim.x + threadIdx.x;
    if (i < n_edges)
        atomicAdd(&g_deg[erow[i]], 1);
}

__global__ void __launch_bounds__(1024)
scan_kernel(int n)
{
    __shared__ int warp_sums[32];
    __shared__ int s_carry;
    int tid = threadIdx.x, lane = tid & 31, wid = tid >> 5;
    if (tid == 0) s_carry = 0;
    __syncthreads();

    for (int base = 0; base < n; base += 1024) {
        int i = base + tid;
        int v = (i < n) ? g_deg[i] : 0;
        int incl = v;
        #pragma unroll
        for (int d = 1; d < 32; d <<= 1) {
            int t = __shfl_up_sync(0xffffffffu, incl, d);
            if (lane >= d) incl += t;
        }
        if (lane == 31) warp_sums[wid] = incl;
        __syncthreads();
        if (wid == 0) {
            int s = warp_sums[lane];
            #pragma unroll
            for (int d = 1; d < 32; d <<= 1) {
                int t = __shfl_up_sync(0xffffffffu, s, d);
                if (lane >= d) s += t;
            }
            warp_sums[lane] = s;
        }
        __syncthreads();
        int warp_off = (wid == 0) ? 0 : warp_sums[wid - 1];
        int excl = s_carry + warp_off + incl - v;
        if (i < n) { g_offs[i] = excl; g_cursor[i] = excl; }
        __syncthreads();
        if (tid == 0) s_carry += warp_sums[31];
        __syncthreads();
    }
    if (threadIdx.x == 0) g_offs[n] = s_carry;
}

__global__ void __launch_bounds__(256)
scatter_kernel(const int* __restrict__ erow, const int* __restrict__ ecol,
               const float* __restrict__ eval_, int n_edges)
{
    int i = blockIdx.x * blockDim.x + threadIdx.x;
    if (i >= n_edges) return;
    int r = erow[i];
    int p = atomicAdd(&g_cursor[r], 1);
    g_epack[p] = make_float2(eval_[i], __int_as_float(ecol[i]));
}

// ---------------------------------------------------------------------------
// Gather: one warp per row; fused (+x2, relu)
// ---------------------------------------------------------------------------
__global__ void __launch_bounds__(256)
gather_kernel(const float* __restrict__ y, float* __restrict__ out, int n_nodes)
{
    int row  = blockIdx.x * (blockDim.x >> 5) + (threadIdx.x >> 5);
    int lane = threadIdx.x & 31;
    if (row >= n_nodes) return;

    int s = g_offs[row];
    int e = g_offs[row + 1];

    float4 acc = make_float4(0.f, 0.f, 0.f, 0.f);

    for (int base = s; base < e; base += 32) {
        int idx = base + lane;
        float2 p = make_float2(0.f, 0.f);
        if (idx < e) p = g_epack[idx];
        int cnt = min(32, e - base);

        int j = 0;
        for (; j + 4 <= cnt; j += 4) {
            float v0 = __shfl_sync(0xffffffffu, p.x, j);
            int   c0 = __float_as_int(__shfl_sync(0xffffffffu, p.y, j));
            float v1 = __shfl_sync(0xffffffffu, p.x, j + 1);
            int   c1 = __float_as_int(__shfl_sync(0xffffffffu, p.y, j + 1));
            float v2 = __shfl_sync(0xffffffffu, p.x, j + 2);
            int   c2 = __float_as_int(__shfl_sync(0xffffffffu, p.y, j + 2));
            float v3 = __shfl_sync(0xffffffffu, p.x, j + 3);
            int   c3 = __float_as_int(__shfl_sync(0xffffffffu, p.y, j + 3));

            float4 m0 = reinterpret_cast<const float4*>(y + (size_t)c0 * D)[lane];
            float4 m1 = reinterpret_cast<const float4*>(y + (size_t)c1 * D)[lane];
            float4 m2 = reinterpret_cast<const float4*>(y + (size_t)c2 * D)[lane];
            float4 m3 = reinterpret_cast<const float4*>(y + (size_t)c3 * D)[lane];

            acc.x += v0 * m0.x; acc.y += v0 * m0.y; acc.z += v0 * m0.z; acc.w += v0 * m0.w;
            acc.x += v1 * m1.x; acc.y += v1 * m1.y; acc.z += v1 * m1.z; acc.w += v1 * m1.w;
            acc.x += v2 * m2.x; acc.y += v2 * m2.y; acc.z += v2 * m2.z; acc.w += v2 * m2.w;
            acc.x += v3 * m3.x; acc.y += v3 * m3.y; acc.z += v3 * m3.z; acc.w += v3 * m3.w;
        }
        for (; j < cnt; ++j) {
            float vj = __shfl_sync(0xffffffffu, p.x, j);
            int   cj = __float_as_int(__shfl_sync(0xffffffffu, p.y, j));
            float4 m = reinterpret_cast<const float4*>(y + (size_t)cj * D)[lane];
            acc.x += vj * m.x; acc.y += vj * m.y; acc.z += vj * m.z; acc.w += vj * m.w;
        }
    }

    float4* orow = reinterpret_cast<float4*>(out + (size_t)row * D);
    float4 x2 = orow[lane];
    acc.x = fmaxf(acc.x + x2.x, 0.f);
    acc.y = fmaxf(acc.y + x2.y, 0.f);
    acc.z = fmaxf(acc.z + x2.z, 0.f);
    acc.w = fmaxf(acc.w + x2.w, 0.f);
    orow[lane] = acc;
}

extern "C" void kernel_launch(void* const* d_in, const int* in_sizes, int n_in,
                              void* d_out, int out_size)
{
    const float* x     = (const float*)d_in[0];
    const int*   erow  = (const int*)  d_in[1];
    const int*   ecol  = (const int*)  d_in[2];
    const float* eval_ = (const float*)d_in[3];
    const float* W     = (const float*)d_in[4];
    const float* b     = (const float*)d_in[5];
    const float* Wself = (const float*)d_in[6];
    const float* bself = (const float*)d_in[7];
    float* out = (float*)d_out;

    int n_nodes = in_sizes[0] / D;
    int n_edges = in_sizes[1];

    float* y;     cudaGetSymbolAddress((void**)&y, g_y);
    int*   degp;  cudaGetSymbolAddress((void**)&degp, g_deg);

    static cudaStream_t sB = nullptr;
    static cudaEvent_t  evFork = nullptr, evJoinB = nullptr;
    const int smem_bytes = SM_WORDS * 4;              // 139264
    if (!sB) {
        cudaStreamCreateWithFlags(&sB, cudaStreamNonBlocking);
        cudaEventCreateWithFlags(&evFork,  cudaEventDisableTiming);
        cudaEventCreateWithFlags(&evJoinB, cudaEventDisableTiming);
        cudaFuncSetAttribute(mma_gemm,
                             cudaFuncAttributeMaxDynamicSharedMemorySize, smem_bytes);
    }

    // Fork: CSR build on side stream, GEMMs on main stream.
    cudaEventRecord(evFork, 0);
    cudaStreamWaitEvent(sB, evFork, 0);

    cudaMemsetAsync(degp, 0, (size_t)n_nodes * sizeof(int), sB);
    hist_kernel<<<(n_edges + 255) / 256, 256, 0, sB>>>(erow, n_edges);
    scan_kernel<<<1, 1024, 0, sB>>>(n_nodes);
    scatter_kernel<<<(n_edges + 255) / 256, 256, 0, sB>>>(erow, ecol, eval_, n_edges);
    cudaEventRecord(evJoinB, sB);

    // Tensor-core GEMMs: y (scratch) and x2 (into out)
    int tiles = (n_nodes + TMG - 1) / TMG;
    dim3 grid(tiles, 2);
    mma_gemm<<<grid, 256, smem_bytes>>>(x, W, b, Wself, bself, y, out, n_nodes);

    // Join, then fused gather (+x2, relu)
    cudaStreamWaitEvent(0, evJoinB, 0);
    int warps_per_block = 256 / 32;
    int gblocks = (n_nodes + warps_per_block - 1) / warps_per_block;
    gather_kernel<<<gblocks, 256>>>(y, out, n_nodes);
}